// round 1
// baseline (speedup 1.0000x reference)
#include <cuda_runtime.h>
#include <cstdint>
#include <cstddef>

// Problem constants
#define BB   2
#define LL   2048
#define MM   (BB*LL)     // 4096 rows
#define DD   768
#define DH   1536
#define NLAY 8
#define VV   50257

// ---------------------------------------------------------------------------
// Scratch (no cudaMalloc allowed -> __device__ globals)
// ---------------------------------------------------------------------------
__device__ float g_x [MM*DD];
__device__ float g_h1[MM*DD];
__device__ float g_h2[MM*DD];
__device__ float g_s [MM*DD];
__device__ float g_g [MM*DD];
__device__ float g_xn[MM*DD];
__device__ float g_dl[MM*DH];
__device__ float g_al[MM*DH];
__device__ float g_bl[MM*DH];
__device__ float g_hs[MM*DH];

__device__ __forceinline__ float siluf(float v) {
    return v * (1.0f / (1.0f + expf(-v)));
}

// ---------------------------------------------------------------------------
// Embedding gather: x[m, :] = embed[tokens[m], :]   (float4 vectorized)
// ---------------------------------------------------------------------------
__global__ void embed_kernel(const int* __restrict__ tokens,
                             const float* __restrict__ embed,
                             float* __restrict__ x) {
    int idx = blockIdx.x * blockDim.x + threadIdx.x;      // over MM * (DD/4)
    const int C4 = DD / 4;                                 // 192
    if (idx >= MM * C4) return;
    int m = idx / C4;
    int c = idx - m * C4;
    int t = tokens[m];
    reinterpret_cast<float4*>(x)[idx] =
        reinterpret_cast<const float4*>(embed + (size_t)t * DD)[c];
}

// ---------------------------------------------------------------------------
// Tiled SGEMM:  C[M,N] = A[M,K] * W[N,K]^T  (+ bias[n]) (+ epilogue)
//   EPI == 0 : C = acc + bias
//   EPI == 1 : C = C + acc + bias       (accumulate into existing C)
//   EPI == 2 : C = acc + S              (add source tensor, no bias)
// 128x128 tile, BK=16, 256 threads, 8x8 per-thread micro-tile.
// M must be a multiple of 128 (true here: 4096). N edge guarded (head).
// K must be a multiple of 16 (768, 1536 OK).
// ---------------------------------------------------------------------------
template<int EPI>
__global__ __launch_bounds__(256)
void gemm_nt(const float* __restrict__ A, const float* __restrict__ W,
             const float* __restrict__ bias, const float* __restrict__ S,
             float* __restrict__ C, int M, int N, int K) {
    __shared__ float As[16][128];
    __shared__ float Bs[16][128];

    const int tid = threadIdx.x;
    const int bm  = blockIdx.y * 128;
    const int bn  = blockIdx.x * 128;

    const int lr = tid >> 2;          // 0..63  (row within tile, +64 on 2nd pass)
    const int lk = (tid & 3) << 2;    // 0,4,8,12 (k offset, float4)
    const int tx = tid & 15;          // 0..15 -> n micro-tile
    const int ty = tid >> 4;          // 0..15 -> m micro-tile

    float acc[8][8];
    #pragma unroll
    for (int i = 0; i < 8; i++)
        #pragma unroll
        for (int j = 0; j < 8; j++)
            acc[i][j] = 0.0f;

    for (int k0 = 0; k0 < K; k0 += 16) {
        #pragma unroll
        for (int rr = 0; rr < 2; rr++) {
            int row = lr + rr * 64;
            float4 av = *reinterpret_cast<const float4*>(
                A + (size_t)(bm + row) * K + k0 + lk);
            As[lk + 0][row] = av.x;
            As[lk + 1][row] = av.y;
            As[lk + 2][row] = av.z;
            As[lk + 3][row] = av.w;

            int n = bn + row;
            float4 wv = make_float4(0.f, 0.f, 0.f, 0.f);
            if (n < N)
                wv = *reinterpret_cast<const float4*>(
                    W + (size_t)n * K + k0 + lk);
            Bs[lk + 0][row] = wv.x;
            Bs[lk + 1][row] = wv.y;
            Bs[lk + 2][row] = wv.z;
            Bs[lk + 3][row] = wv.w;
        }
        __syncthreads();

        #pragma unroll
        for (int k = 0; k < 16; k++) {
            float a[8], b[8];
            *reinterpret_cast<float4*>(&a[0]) =
                *reinterpret_cast<const float4*>(&As[k][ty * 8]);
            *reinterpret_cast<float4*>(&a[4]) =
                *reinterpret_cast<const float4*>(&As[k][ty * 8 + 4]);
            *reinterpret_cast<float4*>(&b[0]) =
                *reinterpret_cast<const float4*>(&Bs[k][tx * 8]);
            *reinterpret_cast<float4*>(&b[4]) =
                *reinterpret_cast<const float4*>(&Bs[k][tx * 8 + 4]);
            #pragma unroll
            for (int i = 0; i < 8; i++)
                #pragma unroll
                for (int j = 0; j < 8; j++)
                    acc[i][j] += a[i] * b[j];
        }
        __syncthreads();
    }

    // epilogue
    #pragma unroll
    for (int i = 0; i < 8; i++) {
        int m = bm + ty * 8 + i;
        #pragma unroll
        for (int j = 0; j < 8; j++) {
            int n = bn + tx * 8 + j;
            if (n < N) {
                float v = acc[i][j];
                if (bias) v += __ldg(&bias[n]);
                size_t idx = (size_t)m * N + n;
                if (EPI == 1) v += C[idx];
                if (EPI == 2) v += S[idx];
                C[idx] = v;
            }
        }
    }
}

// ---------------------------------------------------------------------------
// Depthwise conv1d (k=3, pad=1, per-batch) + SiLU
// ---------------------------------------------------------------------------
__global__ void conv_silu_kernel(const float* __restrict__ h,
                                 const float* __restrict__ cw,   // [DD,3]
                                 const float* __restrict__ cb,   // [DD]
                                 float* __restrict__ o) {
    int idx = blockIdx.x * blockDim.x + threadIdx.x;
    if (idx >= MM * DD) return;
    int e = idx % DD;
    int l = (idx / DD) % LL;
    float w0 = __ldg(&cw[e * 3 + 0]);
    float w1 = __ldg(&cw[e * 3 + 1]);
    float w2 = __ldg(&cw[e * 3 + 2]);
    float c = h[idx] * w1 + __ldg(&cb[e]);
    if (l > 0)      c += h[idx - DD] * w0;
    if (l < LL - 1) c += h[idx + DD] * w2;
    o[idx] = siluf(c);
}

// ---------------------------------------------------------------------------
// SSM scan: per (b, channel) sequential recurrence matching the reference:
//   xd = softplus(dl); A_bar = exp(-xd * al); p *= A_bar; hs += bl * p
// softplus implemented as JAX logaddexp(x,0) = max(x,0) + log1p(exp(-|x|))
// ---------------------------------------------------------------------------
__global__ void scan_kernel(const float* __restrict__ dl,
                            const float* __restrict__ al,
                            const float* __restrict__ bl,
                            float* __restrict__ hs) {
    int gid = blockIdx.x * blockDim.x + threadIdx.x;   // 0 .. BB*DH-1
    if (gid >= BB * DH) return;
    int b = gid / DH;
    int h = gid - b * DH;
    size_t base = (size_t)b * LL * DH + h;
    float p = 1.0f, s = 0.0f;
    for (int t = 0; t < LL; t++) {
        size_t i = base + (size_t)t * DH;
        float xdin = dl[i];
        float xd = fmaxf(xdin, 0.0f) + log1pf(expf(-fabsf(xdin)));
        float ab = expf(-xd * al[i]);
        p *= ab;
        s += bl[i] * p;
        hs[i] = s;
    }
}

// ---------------------------------------------------------------------------
// Gate:  g = s * silu(g)
// ---------------------------------------------------------------------------
__global__ void gate_kernel(const float* __restrict__ s, float* __restrict__ g) {
    int idx = blockIdx.x * blockDim.x + threadIdx.x;
    if (idx >= MM * DD) return;
    g[idx] = s[idx] * siluf(g[idx]);
}

// ---------------------------------------------------------------------------
// LayerNorm over last dim (768); one block (256 threads) per row
// ---------------------------------------------------------------------------
__global__ __launch_bounds__(256)
void ln_kernel(const float* __restrict__ x, const float* __restrict__ gw,
               const float* __restrict__ bw, float* __restrict__ y) {
    int row = blockIdx.x;
    const float* xr = x + (size_t)row * DD;
    float* yr = y + (size_t)row * DD;
    int tid = threadIdx.x;

    __shared__ float red[8];
    __shared__ float stat[2];

    float v[3];
    float sum = 0.0f;
    #pragma unroll
    for (int i = 0; i < 3; i++) { v[i] = xr[tid + i * 256]; sum += v[i]; }
    #pragma unroll
    for (int o = 16; o > 0; o >>= 1) sum += __shfl_xor_sync(0xffffffffu, sum, o);
    if ((tid & 31) == 0) red[tid >> 5] = sum;
    __syncthreads();
    if (tid == 0) {
        float t = 0.0f;
        #pragma unroll
        for (int w = 0; w < 8; w++) t += red[w];
        stat[0] = t;
    }
    __syncthreads();
    float mu = stat[0] * (1.0f / (float)DD);

    float vs = 0.0f;
    #pragma unroll
    for (int i = 0; i < 3; i++) { float d = v[i] - mu; vs += d * d; }
    #pragma unroll
    for (int o = 16; o > 0; o >>= 1) vs += __shfl_xor_sync(0xffffffffu, vs, o);
    if ((tid & 31) == 0) red[tid >> 5] = vs;
    __syncthreads();
    if (tid == 0) {
        float t = 0.0f;
        #pragma unroll
        for (int w = 0; w < 8; w++) t += red[w];
        stat[1] = t;
    }
    __syncthreads();
    float rstd = rsqrtf(stat[1] * (1.0f / (float)DD) + 1e-5f);

    #pragma unroll
    for (int i = 0; i < 3; i++) {
        int e = tid + i * 256;
        yr[e] = (v[i] - mu) * rstd * __ldg(&gw[e]) + __ldg(&bw[e]);
    }
}

// ---------------------------------------------------------------------------
// Launcher
// ---------------------------------------------------------------------------
extern "C" void kernel_launch(void* const* d_in, const int* in_sizes, int n_in,
                              void* d_out, int out_size) {
    const int*   tokens  = (const int*)  d_in[0];
    const float* embed   = (const float*)d_in[1];
    const float* lin1_w  = (const float*)d_in[2];
    const float* conv_w  = (const float*)d_in[3];
    const float* conv_b  = (const float*)d_in[4];
    const float* A_w     = (const float*)d_in[5];
    const float* A_b     = (const float*)d_in[6];
    const float* B_w     = (const float*)d_in[7];
    const float* B_b     = (const float*)d_in[8];
    const float* del_w   = (const float*)d_in[9];
    const float* del_b   = (const float*)d_in[10];
    const float* C_w     = (const float*)d_in[11];
    const float* C_b     = (const float*)d_in[12];
    const float* D_w     = (const float*)d_in[13];
    const float* D_b     = (const float*)d_in[14];
    const float* lin2_w  = (const float*)d_in[15];
    const float* last_w  = (const float*)d_in[16];
    const float* ln_g    = (const float*)d_in[17];
    const float* ln_b    = (const float*)d_in[18];
    float* out = (float*)d_out;

    float *x, *h1, *h2, *s, *g, *xn, *dl, *al, *bl, *hs;
    cudaGetSymbolAddress((void**)&x,  g_x);
    cudaGetSymbolAddress((void**)&h1, g_h1);
    cudaGetSymbolAddress((void**)&h2, g_h2);
    cudaGetSymbolAddress((void**)&s,  g_s);
    cudaGetSymbolAddress((void**)&g,  g_g);
    cudaGetSymbolAddress((void**)&xn, g_xn);
    cudaGetSymbolAddress((void**)&dl, g_dl);
    cudaGetSymbolAddress((void**)&al, g_al);
    cudaGetSymbolAddress((void**)&bl, g_bl);
    cudaGetSymbolAddress((void**)&hs, g_hs);

    const dim3 blk(256);
    const dim3 gd768((DD + 127) / 128, MM / 128);     // 6 x 32
    const dim3 gd1536((DH + 127) / 128, MM / 128);    // 12 x 32
    const dim3 gdV((VV + 127) / 128, MM / 128);       // 393 x 32

    // embedding
    embed_kernel<<<(MM * (DD / 4) + 255) / 256, 256>>>(tokens, embed, x);

    for (int i = 0; i < NLAY; i++) {
        const float* l1w = lin1_w + (size_t)i * DD * DD;
        const float* cw  = conv_w + (size_t)i * DD * 3;
        const float* cb  = conv_b + (size_t)i * DD;
        const float* dw  = del_w  + (size_t)i * DH * DD;
        const float* db  = del_b  + (size_t)i * DH;
        const float* aw  = A_w    + (size_t)i * DH * DD;
        const float* ab  = A_b    + (size_t)i * DH;
        const float* bwp = B_w    + (size_t)i * DH * DD;
        const float* bbp = B_b    + (size_t)i * DH;
        const float* cwp = C_w    + (size_t)i * DD * DH;
        const float* cbp = C_b    + (size_t)i * DD;
        const float* dwp = D_w    + (size_t)i * DD * DD;
        const float* dbp = D_b    + (size_t)i * DD;
        const float* l2w = lin2_w + (size_t)i * DD * DD;
        const float* lw  = last_w + (size_t)i * DD * DD;

        // h1 = x @ lin1^T
        gemm_nt<0><<<gd768, blk>>>(x, l1w, nullptr, nullptr, h1, MM, DD, DD);
        // h2 = silu(conv1d(h1))
        conv_silu_kernel<<<(MM * DD + 255) / 256, 256>>>(h1, cw, cb, h2);
        // delta / A / B projections
        gemm_nt<0><<<gd1536, blk>>>(h2, dw,  db,  nullptr, dl, MM, DH, DD);
        gemm_nt<0><<<gd1536, blk>>>(h2, aw,  ab,  nullptr, al, MM, DH, DD);
        gemm_nt<0><<<gd1536, blk>>>(h2, bwp, bbp, nullptr, bl, MM, DH, DD);
        // SSM scan
        scan_kernel<<<(BB * DH + 255) / 256, 256>>>(dl, al, bl, hs);
        // s = hs @ Cw^T + Cb  +  h2 @ Dw^T + Db
        gemm_nt<0><<<gd768, blk>>>(hs, cwp, cbp, nullptr, s, MM, DD, DH);
        gemm_nt<1><<<gd768, blk>>>(h2, dwp, dbp, nullptr, s, MM, DD, DD);
        // g = s @ lin2^T ; g = s * silu(g)
        gemm_nt<0><<<gd768, blk>>>(s, l2w, nullptr, nullptr, g, MM, DD, DD);
        gate_kernel<<<(MM * DD + 255) / 256, 256>>>(s, g);
        // x = s + g @ last^T
        gemm_nt<2><<<gd768, blk>>>(g, lw, nullptr, s, x, MM, DD, DD);
    }

    // LayerNorm
    ln_kernel<<<MM, 256>>>(x, ln_g, ln_b, xn);
    // tied head: out = xn @ embed^T  [4096, 50257]
    gemm_nt<0><<<gdV, blk>>>(xn, embed, nullptr, nullptr, out, MM, VV, DD);
}

// round 3
// speedup vs baseline: 1.7904x; 1.7904x over previous
#include <cuda_runtime.h>
#include <cuda_bf16.h>
#include <cstdint>
#include <cstddef>

// Problem constants
#define BB   2
#define LL   2048
#define MM   (BB*LL)     // 4096 rows
#define DD   768
#define DH   1536
#define NLAY 8
#define VV   50257

// ---------------------------------------------------------------------------
// Scratch (no cudaMalloc allowed -> __device__ globals)
// ---------------------------------------------------------------------------
__device__ float g_x [MM*DD];
__device__ float g_h1[MM*DD];
__device__ float g_h2[MM*DD];
__device__ float g_s [MM*DD];
__device__ float g_g [MM*DD];
__device__ float g_xn[MM*DD];
__device__ float g_dl[MM*DH];
__device__ float g_al[MM*DH];
__device__ float g_bl[MM*DH];
__device__ float g_hs[MM*DH];

__device__ __forceinline__ float siluf(float v) {
    return v * (1.0f / (1.0f + expf(-v)));
}

// ---------------------------------------------------------------------------
// Embedding gather
// ---------------------------------------------------------------------------
__global__ void embed_kernel(const int* __restrict__ tokens,
                             const float* __restrict__ embed,
                             float* __restrict__ x) {
    int idx = blockIdx.x * blockDim.x + threadIdx.x;      // over MM * (DD/4)
    const int C4 = DD / 4;                                 // 192
    if (idx >= MM * C4) return;
    int m = idx / C4;
    int c = idx - m * C4;
    int t = tokens[m];
    reinterpret_cast<float4*>(x)[idx] =
        reinterpret_cast<const float4*>(embed + (size_t)t * DD)[c];
}

// ---------------------------------------------------------------------------
// BF16x3 split-precision tensor-core GEMM:
//   C[M,N] = A[M,K] * W[N,K]^T (+bias) (+epilogue)
//   Each fp32 operand split hi/lo bf16; 3 MMAs: lo*hi + hi*lo + hi*hi.
//   EPI == 0 : C = acc + bias
//   EPI == 1 : C = C + acc + bias
//   EPI == 2 : C = acc + S
// 128x128 block tile, BK=16, 256 threads (8 warps, 2x4 of 64x32 warp tiles),
// mma.sync m16n8k16 bf16, cp.async double buffered. M%128==0, K%16==0, N guarded.
// ---------------------------------------------------------------------------
#define BM 128
#define BN 128
#define BKT 16
#define PITCH 20

__device__ __forceinline__ void cp_async16(void* sdst, const void* gsrc, bool pred) {
    unsigned saddr = (unsigned)__cvta_generic_to_shared(sdst);
    int sz = pred ? 16 : 0;
    asm volatile("cp.async.cg.shared.global [%0], [%1], 16, %2;\n"
                 :: "r"(saddr), "l"(gsrc), "r"(sz));
}

// Split two floats into packed bf16x2 hi and lo parts (low half = x0).
__device__ __forceinline__ void split_pair(float x0, float x1,
                                           uint32_t& hi, uint32_t& lo) {
    uint32_t h;
    asm("cvt.rn.bf16x2.f32 %0, %1, %2;" : "=r"(h) : "f"(x1), "f"(x0));
    hi = h;
    float h0 = __uint_as_float(h << 16);
    float h1 = __uint_as_float(h & 0xffff0000u);
    float r0 = x0 - h0;
    float r1 = x1 - h1;
    asm("cvt.rn.bf16x2.f32 %0, %1, %2;" : "=r"(lo) : "f"(r1), "f"(r0));
}

__device__ __forceinline__ void mma16(float* c, const uint32_t* a, const uint32_t* b) {
    asm volatile(
        "mma.sync.aligned.m16n8k16.row.col.f32.bf16.bf16.f32 "
        "{%0,%1,%2,%3}, {%4,%5,%6,%7}, {%8,%9}, {%0,%1,%2,%3};"
        : "+f"(c[0]), "+f"(c[1]), "+f"(c[2]), "+f"(c[3])
        : "r"(a[0]), "r"(a[1]), "r"(a[2]), "r"(a[3]), "r"(b[0]), "r"(b[1]));
}

template<int EPI>
__global__ __launch_bounds__(256, 1)
void gemm_bf16x3(const float* __restrict__ A, const float* __restrict__ W,
                 const float* __restrict__ bias, const float* __restrict__ S,
                 float* __restrict__ C, int M, int N, int K) {
    __shared__ float As[2][BM][PITCH];
    __shared__ float Bs[2][BN][PITCH];

    const int tid  = threadIdx.x;
    const int warp = tid >> 5;
    const int lane = tid & 31;
    const int g    = lane >> 2;     // 0..7
    const int t4   = lane & 3;      // 0..3
    const int wm   = (warp & 1) * 64;
    const int wn   = (warp >> 1) * 32;
    const int bm   = blockIdx.y * BM;
    const int bn   = blockIdx.x * BN;

    float acc[4][4][4];
    #pragma unroll
    for (int mt = 0; mt < 4; mt++)
        #pragma unroll
        for (int nt = 0; nt < 4; nt++)
            #pragma unroll
            for (int r = 0; r < 4; r++)
                acc[mt][nt][r] = 0.0f;

    const int T = K / BKT;

    // stage-0 loads
    {
        #pragma unroll
        for (int i = 0; i < 2; i++) {
            int c = tid + i * 256;        // 0..511
            int r = c >> 2, kc = (c & 3) * 4;
            cp_async16(&As[0][r][kc], A + (size_t)(bm + r) * K + kc, true);
            bool p = (bn + r) < N;
            const float* src = W + (size_t)(p ? (bn + r) : 0) * K + kc;
            cp_async16(&Bs[0][r][kc], src, p);
        }
        asm volatile("cp.async.commit_group;");
    }

    for (int tI = 0; tI < T; tI++) {
        const int s = tI & 1;
        if (tI + 1 < T) {
            const int k0 = (tI + 1) * BKT;
            const int sn = s ^ 1;
            #pragma unroll
            for (int i = 0; i < 2; i++) {
                int c = tid + i * 256;
                int r = c >> 2, kc = (c & 3) * 4;
                cp_async16(&As[sn][r][kc], A + (size_t)(bm + r) * K + k0 + kc, true);
                bool p = (bn + r) < N;
                const float* src = W + (size_t)(p ? (bn + r) : 0) * K + k0 + kc;
                cp_async16(&Bs[sn][r][kc], src, p);
            }
            asm volatile("cp.async.commit_group;");
            asm volatile("cp.async.wait_group 1;");
        } else {
            asm volatile("cp.async.wait_group 0;");
        }
        __syncthreads();

        // one m16n8k16 step covers the full BKT=16 slice
        uint32_t ahi[4][4], alo[4][4], bhi[4][2], blo[4][2];
        const int kl = 2 * t4;       // k cols 0..7 region
        const int kh = 2 * t4 + 8;   // k cols 8..15 region

        #pragma unroll
        for (int mt = 0; mt < 4; mt++) {
            int m = wm + mt * 16;
            float2 p0 = *reinterpret_cast<const float2*>(&As[s][m + g    ][kl]);
            float2 p1 = *reinterpret_cast<const float2*>(&As[s][m + g + 8][kl]);
            float2 p2 = *reinterpret_cast<const float2*>(&As[s][m + g    ][kh]);
            float2 p3 = *reinterpret_cast<const float2*>(&As[s][m + g + 8][kh]);
            split_pair(p0.x, p0.y, ahi[mt][0], alo[mt][0]);
            split_pair(p1.x, p1.y, ahi[mt][1], alo[mt][1]);
            split_pair(p2.x, p2.y, ahi[mt][2], alo[mt][2]);
            split_pair(p3.x, p3.y, ahi[mt][3], alo[mt][3]);
        }
        #pragma unroll
        for (int nt = 0; nt < 4; nt++) {
            int n = wn + nt * 8;
            float2 q0 = *reinterpret_cast<const float2*>(&Bs[s][n + g][kl]);
            float2 q1 = *reinterpret_cast<const float2*>(&Bs[s][n + g][kh]);
            split_pair(q0.x, q0.y, bhi[nt][0], blo[nt][0]);
            split_pair(q1.x, q1.y, bhi[nt][1], blo[nt][1]);
        }

        #pragma unroll
        for (int mt = 0; mt < 4; mt++)
            #pragma unroll
            for (int nt = 0; nt < 4; nt++) {
                mma16(acc[mt][nt], alo[mt], bhi[nt]);   // small terms first
                mma16(acc[mt][nt], ahi[mt], blo[nt]);
                mma16(acc[mt][nt], ahi[mt], bhi[nt]);
            }
        __syncthreads();
    }

    // epilogue
    #pragma unroll
    for (int mt = 0; mt < 4; mt++) {
        #pragma unroll
        for (int i = 0; i < 2; i++) {
            int m = bm + wm + mt * 16 + g + i * 8;
            #pragma unroll
            for (int nt = 0; nt < 4; nt++) {
                int n0 = bn + wn + nt * 8 + t4 * 2;
                #pragma unroll
                for (int j = 0; j < 2; j++) {
                    int n = n0 + j;
                    if (n < N) {
                        float v = acc[mt][nt][i * 2 + j];
                        if (bias) v += __ldg(&bias[n]);
                        size_t idx = (size_t)m * N + n;
                        if (EPI == 1) v += C[idx];
                        if (EPI == 2) v += S[idx];
                        C[idx] = v;
                    }
                }
            }
        }
    }
}

// ---------------------------------------------------------------------------
// Depthwise conv1d (k=3, pad=1) + SiLU
// ---------------------------------------------------------------------------
__global__ void conv_silu_kernel(const float* __restrict__ h,
                                 const float* __restrict__ cw,
                                 const float* __restrict__ cb,
                                 float* __restrict__ o) {
    int idx = blockIdx.x * blockDim.x + threadIdx.x;
    if (idx >= MM * DD) return;
    int e = idx % DD;
    int l = (idx / DD) % LL;
    float w0 = __ldg(&cw[e * 3 + 0]);
    float w1 = __ldg(&cw[e * 3 + 1]);
    float w2 = __ldg(&cw[e * 3 + 2]);
    float c = h[idx] * w1 + __ldg(&cb[e]);
    if (l > 0)      c += h[idx - DD] * w0;
    if (l < LL - 1) c += h[idx + DD] * w2;
    o[idx] = siluf(c);
}

// ---------------------------------------------------------------------------
// Elementwise A_bar: al <- exp(-softplus(dl) * al)
// ---------------------------------------------------------------------------
__global__ void abar_kernel(const float* __restrict__ dl, float* __restrict__ al) {
    int idx = blockIdx.x * blockDim.x + threadIdx.x;
    if (idx >= MM * DH) return;
    float xdin = dl[idx];
    float xd = fmaxf(xdin, 0.0f) + log1pf(expf(-fabsf(xdin)));
    al[idx] = expf(-xd * al[idx]);
}

// ---------------------------------------------------------------------------
// SSM scan: p *= A_bar[t]; s += B_x[t]*p (sequential over L, parallel over B*DH)
// ---------------------------------------------------------------------------
__global__ void scan_kernel(const float* __restrict__ ab,
                            const float* __restrict__ bl,
                            float* __restrict__ hs) {
    int gid = blockIdx.x * blockDim.x + threadIdx.x;   // 0 .. BB*DH-1
    if (gid >= BB * DH) return;
    int b = gid / DH;
    int h = gid - b * DH;
    size_t base = (size_t)b * LL * DH + h;
    float p = 1.0f, s = 0.0f;
    for (int t = 0; t < LL; t += 4) {
        size_t i = base + (size_t)t * DH;
        float a0 = ab[i], a1 = ab[i + DH], a2 = ab[i + 2 * DH], a3 = ab[i + 3 * DH];
        float b0 = bl[i], b1 = bl[i + DH], b2 = bl[i + 2 * DH], b3 = bl[i + 3 * DH];
        float p0 = p * a0;
        float p1 = p0 * a1;
        float p2 = p1 * a2;
        float p3 = p2 * a3;
        s = fmaf(b0, p0, s); hs[i] = s;
        s = fmaf(b1, p1, s); hs[i + DH] = s;
        s = fmaf(b2, p2, s); hs[i + 2 * DH] = s;
        s = fmaf(b3, p3, s); hs[i + 3 * DH] = s;
        p = p3;
    }
}

// ---------------------------------------------------------------------------
// Gate:  g = s * silu(g)
// ---------------------------------------------------------------------------
__global__ void gate_kernel(const float* __restrict__ s, float* __restrict__ g) {
    int idx = blockIdx.x * blockDim.x + threadIdx.x;
    if (idx >= MM * DD) return;
    g[idx] = s[idx] * siluf(g[idx]);
}

// ---------------------------------------------------------------------------
// LayerNorm over last dim (768)
// ---------------------------------------------------------------------------
__global__ __launch_bounds__(256)
void ln_kernel(const float* __restrict__ x, const float* __restrict__ gw,
               const float* __restrict__ bw, float* __restrict__ y) {
    int row = blockIdx.x;
    const float* xr = x + (size_t)row * DD;
    float* yr = y + (size_t)row * DD;
    int tid = threadIdx.x;

    __shared__ float red[8];
    __shared__ float stat[2];

    float v[3];
    float sum = 0.0f;
    #pragma unroll
    for (int i = 0; i < 3; i++) { v[i] = xr[tid + i * 256]; sum += v[i]; }
    #pragma unroll
    for (int o = 16; o > 0; o >>= 1) sum += __shfl_xor_sync(0xffffffffu, sum, o);
    if ((tid & 31) == 0) red[tid >> 5] = sum;
    __syncthreads();
    if (tid == 0) {
        float t = 0.0f;
        #pragma unroll
        for (int w = 0; w < 8; w++) t += red[w];
        stat[0] = t;
    }
    __syncthreads();
    float mu = stat[0] * (1.0f / (float)DD);

    float vs = 0.0f;
    #pragma unroll
    for (int i = 0; i < 3; i++) { float d = v[i] - mu; vs += d * d; }
    #pragma unroll
    for (int o = 16; o > 0; o >>= 1) vs += __shfl_xor_sync(0xffffffffu, vs, o);
    if ((tid & 31) == 0) red[tid >> 5] = vs;
    __syncthreads();
    if (tid == 0) {
        float t = 0.0f;
        #pragma unroll
        for (int w = 0; w < 8; w++) t += red[w];
        stat[1] = t;
    }
    __syncthreads();
    float rstd = rsqrtf(stat[1] * (1.0f / (float)DD) + 1e-5f);

    #pragma unroll
    for (int i = 0; i < 3; i++) {
        int e = tid + i * 256;
        yr[e] = (v[i] - mu) * rstd * __ldg(&gw[e]) + __ldg(&bw[e]);
    }
}

// ---------------------------------------------------------------------------
// Launcher
// ---------------------------------------------------------------------------
extern "C" void kernel_launch(void* const* d_in, const int* in_sizes, int n_in,
                              void* d_out, int out_size) {
    const int*   tokens  = (const int*)  d_in[0];
    const float* embed   = (const float*)d_in[1];
    const float* lin1_w  = (const float*)d_in[2];
    const float* conv_w  = (const float*)d_in[3];
    const float* conv_b  = (const float*)d_in[4];
    const float* A_w     = (const float*)d_in[5];
    const float* A_b     = (const float*)d_in[6];
    const float* B_w     = (const float*)d_in[7];
    const float* B_b     = (const float*)d_in[8];
    const float* del_w   = (const float*)d_in[9];
    const float* del_b   = (const float*)d_in[10];
    const float* C_w     = (const float*)d_in[11];
    const float* C_b     = (const float*)d_in[12];
    const float* D_w     = (const float*)d_in[13];
    const float* D_b     = (const float*)d_in[14];
    const float* lin2_w  = (const float*)d_in[15];
    const float* last_w  = (const float*)d_in[16];
    const float* ln_g    = (const float*)d_in[17];
    const float* ln_b    = (const float*)d_in[18];
    float* out = (float*)d_out;

    float *x, *h1, *h2, *s, *g, *xn, *dl, *al, *bl, *hs;
    cudaGetSymbolAddress((void**)&x,  g_x);
    cudaGetSymbolAddress((void**)&h1, g_h1);
    cudaGetSymbolAddress((void**)&h2, g_h2);
    cudaGetSymbolAddress((void**)&s,  g_s);
    cudaGetSymbolAddress((void**)&g,  g_g);
    cudaGetSymbolAddress((void**)&xn, g_xn);
    cudaGetSymbolAddress((void**)&dl, g_dl);
    cudaGetSymbolAddress((void**)&al, g_al);
    cudaGetSymbolAddress((void**)&bl, g_bl);
    cudaGetSymbolAddress((void**)&hs, g_hs);

    const dim3 blk(256);
    const dim3 gd768((DD + 127) / 128, MM / 128);     // 6 x 32
    const dim3 gd1536((DH + 127) / 128, MM / 128);    // 12 x 32
    const dim3 gdV((VV + 127) / 128, MM / 128);       // 393 x 32

    embed_kernel<<<(MM * (DD / 4) + 255) / 256, 256>>>(tokens, embed, x);

    for (int i = 0; i < NLAY; i++) {
        const float* l1w = lin1_w + (size_t)i * DD * DD;
        const float* cw  = conv_w + (size_t)i * DD * 3;
        const float* cb  = conv_b + (size_t)i * DD;
        const float* dw  = del_w  + (size_t)i * DH * DD;
        const float* db  = del_b  + (size_t)i * DH;
        const float* aw  = A_w    + (size_t)i * DH * DD;
        const float* ab  = A_b    + (size_t)i * DH;
        const float* bwp = B_w    + (size_t)i * DH * DD;
        const float* bbp = B_b    + (size_t)i * DH;
        const float* cwp = C_w    + (size_t)i * DD * DH;
        const float* cbp = C_b    + (size_t)i * DD;
        const float* dwp = D_w    + (size_t)i * DD * DD;
        const float* dbp = D_b    + (size_t)i * DD;
        const float* l2w = lin2_w + (size_t)i * DD * DD;
        const float* lw  = last_w + (size_t)i * DD * DD;

        // h1 = x @ lin1^T
        gemm_bf16x3<0><<<gd768, blk>>>(x, l1w, nullptr, nullptr, h1, MM, DD, DD);
        // h2 = silu(conv1d(h1))
        conv_silu_kernel<<<(MM * DD + 255) / 256, 256>>>(h1, cw, cb, h2);
        // delta / A / B projections
        gemm_bf16x3<0><<<gd1536, blk>>>(h2, dw,  db,  nullptr, dl, MM, DH, DD);
        gemm_bf16x3<0><<<gd1536, blk>>>(h2, aw,  ab,  nullptr, al, MM, DH, DD);
        gemm_bf16x3<0><<<gd1536, blk>>>(h2, bwp, bbp, nullptr, bl, MM, DH, DD);
        // A_bar elementwise, then sequential scan
        abar_kernel<<<(MM * DH + 255) / 256, 256>>>(dl, al);
        scan_kernel<<<(BB * DH + 255) / 256, 256>>>(al, bl, hs);
        // s = hs @ Cw^T + Cb  +  h2 @ Dw^T + Db
        gemm_bf16x3<0><<<gd768, blk>>>(hs, cwp, cbp, nullptr, s, MM, DD, DH);
        gemm_bf16x3<1><<<gd768, blk>>>(h2, dwp, dbp, nullptr, s, MM, DD, DD);
        // g = s @ lin2^T ; g = s * silu(g)
        gemm_bf16x3<0><<<gd768, blk>>>(s, l2w, nullptr, nullptr, g, MM, DD, DD);
        gate_kernel<<<(MM * DD + 255) / 256, 256>>>(s, g);
        // x = s + g @ last^T
        gemm_bf16x3<2><<<gd768, blk>>>(g, lw, nullptr, s, x, MM, DD, DD);
    }

    ln_kernel<<<MM, 256>>>(x, ln_g, ln_b, xn);
    gemm_bf16x3<0><<<gdV, blk>>>(xn, embed, nullptr, nullptr, out, MM, VV, DD);
}

// round 4
// speedup vs baseline: 2.6206x; 1.4637x over previous
#include <cuda_runtime.h>
#include <cuda_bf16.h>
#include <cstdint>
#include <cstddef>

typedef __nv_bfloat16 bf16;

// Problem constants
#define BB   2
#define LL   2048
#define MM   (BB*LL)     // 4096 rows
#define DD   768
#define DH   1536
#define NLAY 8
#define VV   50257

// ---------------------------------------------------------------------------
// Scratch (__device__ globals; no cudaMalloc allowed)
// ---------------------------------------------------------------------------
__device__ float g_x [MM*DD];
__device__ float g_h1[MM*DD];
__device__ float g_s [MM*DD];
__device__ float g_g [MM*DD];
__device__ float g_dl[MM*DH];
__device__ float g_al[MM*DH];
__device__ float g_bl[MM*DH];

// Activation hi/lo bf16 planes
__device__ __align__(16) bf16 x_h [MM*DD], x_l [MM*DD];
__device__ __align__(16) bf16 h2_h[MM*DD], h2_l[MM*DD];
__device__ __align__(16) bf16 s_h [MM*DD], s_l [MM*DD];
__device__ __align__(16) bf16 gg_h[MM*DD], gg_l[MM*DD];
__device__ __align__(16) bf16 xn_h[MM*DD], xn_l[MM*DD];
__device__ __align__(16) bf16 hs_h[MM*DH], hs_l[MM*DH];

// Weight hi/lo bf16 planes (all layers)
__device__ __align__(16) bf16 w1_h [NLAY*DD*DD], w1_l [NLAY*DD*DD];
__device__ __align__(16) bf16 wd_h [NLAY*DH*DD], wd_l [NLAY*DH*DD];
__device__ __align__(16) bf16 wa_h [NLAY*DH*DD], wa_l [NLAY*DH*DD];
__device__ __align__(16) bf16 wb_h [NLAY*DH*DD], wb_l [NLAY*DH*DD];
__device__ __align__(16) bf16 wc_h [NLAY*DD*DH], wc_l [NLAY*DD*DH];
__device__ __align__(16) bf16 wD_h [NLAY*DD*DD], wD_l [NLAY*DD*DD];
__device__ __align__(16) bf16 w2_h [NLAY*DD*DD], w2_l [NLAY*DD*DD];
__device__ __align__(16) bf16 wL_h [NLAY*DD*DD], wL_l [NLAY*DD*DD];
__device__ __align__(16) bf16 we_h [VV*DD],      we_l [VV*DD];

__device__ __forceinline__ float siluf(float v) {
    return v * (1.0f / (1.0f + expf(-v)));
}

// Split two floats into packed bf16x2 (low half = x0) hi and lo.
__device__ __forceinline__ void split2(float x0, float x1, uint32_t& hi, uint32_t& lo) {
    asm("cvt.rn.bf16x2.f32 %0, %1, %2;" : "=r"(hi) : "f"(x1), "f"(x0));
    float h0 = __uint_as_float(hi << 16);
    float h1 = __uint_as_float(hi & 0xffff0000u);
    asm("cvt.rn.bf16x2.f32 %0, %1, %2;" : "=r"(lo) : "f"(x1 - h1), "f"(x0 - h0));
}

// ---------------------------------------------------------------------------
// fp32 -> hi/lo bf16 planes (n/4 threads, vectorized)
// ---------------------------------------------------------------------------
__global__ void split_kernel(const float* __restrict__ in,
                             bf16* __restrict__ hi, bf16* __restrict__ lo, int n4) {
    int i = blockIdx.x * blockDim.x + threadIdx.x;
    if (i >= n4) return;
    float4 v = reinterpret_cast<const float4*>(in)[i];
    uint32_t h0, l0, h1, l1;
    split2(v.x, v.y, h0, l0);
    split2(v.z, v.w, h1, l1);
    reinterpret_cast<uint2*>(hi)[i] = make_uint2(h0, h1);
    reinterpret_cast<uint2*>(lo)[i] = make_uint2(l0, l1);
}

// ---------------------------------------------------------------------------
// Embedding gather -> x fp32 + hi/lo planes
// ---------------------------------------------------------------------------
__global__ void embed_kernel(const int* __restrict__ tokens,
                             const float* __restrict__ embed,
                             float* __restrict__ x,
                             bf16* __restrict__ xh, bf16* __restrict__ xl) {
    int idx = blockIdx.x * blockDim.x + threadIdx.x;      // over MM * (DD/4)
    const int C4 = DD / 4;
    if (idx >= MM * C4) return;
    int m = idx / C4;
    int c = idx - m * C4;
    int t = tokens[m];
    float4 v = reinterpret_cast<const float4*>(embed + (size_t)t * DD)[c];
    reinterpret_cast<float4*>(x)[idx] = v;
    uint32_t h0, l0, h1, l1;
    split2(v.x, v.y, h0, l0);
    split2(v.z, v.w, h1, l1);
    reinterpret_cast<uint2*>(xh)[idx] = make_uint2(h0, h1);
    reinterpret_cast<uint2*>(xl)[idx] = make_uint2(l0, l1);
}

// ---------------------------------------------------------------------------
// BF16x3 GEMM with pre-split planes.
//   C[M,N] = A[M,K] * W[N,K]^T  via hh + lh + hl MMA passes.
//   EPI 0: C = acc + bias ; EPI 1: C += acc + bias ; EPI 2: C = acc + S
//   SPLIT: additionally emit hi/lo bf16 planes of the result.
// 128x128 tile, BK=32, 256 thr (8 warps: 2x4 of 64x32), cp.async 2-stage.
// ---------------------------------------------------------------------------
#define BK 32
#define PITCH 20                       // uint32 per SMEM row (16 used)
#define ARRS (128*PITCH)               // one plane array
#define SMEMB (2*4*ARRS*4)             // bytes: 2 stages * 4 arrays

__device__ __forceinline__ void cp_async16(void* sdst, const void* gsrc, bool pred) {
    unsigned saddr = (unsigned)__cvta_generic_to_shared(sdst);
    int sz = pred ? 16 : 0;
    asm volatile("cp.async.cg.shared.global [%0], [%1], 16, %2;\n"
                 :: "r"(saddr), "l"(gsrc), "r"(sz));
}

__device__ __forceinline__ void mma16(float* c, const uint32_t* a, const uint32_t* b) {
    asm volatile(
        "mma.sync.aligned.m16n8k16.row.col.f32.bf16.bf16.f32 "
        "{%0,%1,%2,%3}, {%4,%5,%6,%7}, {%8,%9}, {%0,%1,%2,%3};"
        : "+f"(c[0]), "+f"(c[1]), "+f"(c[2]), "+f"(c[3])
        : "r"(a[0]), "r"(a[1]), "r"(a[2]), "r"(a[3]), "r"(b[0]), "r"(b[1]));
}

template<int EPI, bool SPLIT>
__global__ __launch_bounds__(256, 2)
void gemm_bf3(const bf16* __restrict__ Ah, const bf16* __restrict__ Al,
              const bf16* __restrict__ Wh, const bf16* __restrict__ Wl,
              const float* __restrict__ bias, const float* __restrict__ S,
              float* __restrict__ C, bf16* __restrict__ Ch, bf16* __restrict__ Cl,
              int M, int N, int K) {
    extern __shared__ uint32_t sm[];

    const int tid  = threadIdx.x;
    const int warp = tid >> 5;
    const int lane = tid & 31;
    const int g    = lane >> 2;
    const int t4   = lane & 3;
    const int wm   = (warp & 1) * 64;
    const int wn   = (warp >> 1) * 32;
    const int bm   = blockIdx.y * 128;
    const int bn   = blockIdx.x * 128;

    float acc[4][4][4];
    #pragma unroll
    for (int mt = 0; mt < 4; mt++)
        #pragma unroll
        for (int nt = 0; nt < 4; nt++)
            #pragma unroll
            for (int r = 0; r < 4; r++)
                acc[mt][nt][r] = 0.0f;

    const int T = K / BK;

    // tile loader: 8 cp.async / thread / stage
    auto load_stage = [&](int stage, int k0) {
        uint32_t* base = sm + stage * 4 * ARRS;
        #pragma unroll
        for (int i = 0; i < 2; i++) {
            int cc = tid + i * 256;          // 0..511
            int r  = cc >> 2;                // 0..127
            int kc = (cc & 3) * 8;           // bf16 elem offset within BK
            uint32_t* dst = base + r * PITCH + (kc >> 1);
            cp_async16(dst,            Ah + (size_t)(bm + r) * K + k0 + kc, true);
            cp_async16(dst + ARRS,     Al + (size_t)(bm + r) * K + k0 + kc, true);
            bool p = (bn + r) < N;
            size_t wr = (size_t)(p ? bn + r : 0);
            cp_async16(dst + 2 * ARRS, Wh + wr * K + k0 + kc, p);
            cp_async16(dst + 3 * ARRS, Wl + wr * K + k0 + kc, p);
        }
        asm volatile("cp.async.commit_group;");
    };

    load_stage(0, 0);

    for (int tI = 0; tI < T; tI++) {
        const int s = tI & 1;
        if (tI + 1 < T) {
            load_stage(s ^ 1, (tI + 1) * BK);
            asm volatile("cp.async.wait_group 1;");
        } else {
            asm volatile("cp.async.wait_group 0;");
        }
        __syncthreads();

        const uint32_t* AH = sm + s * 4 * ARRS;
        const uint32_t* AL = AH + ARRS;
        const uint32_t* BH = AH + 2 * ARRS;
        const uint32_t* BL = AH + 3 * ARRS;

        #pragma unroll
        for (int kb = 0; kb < 16; kb += 8) {          // two k16 steps per BK=32
            uint32_t ahi[4][4], bhi[4][2];
            #pragma unroll
            for (int mt = 0; mt < 4; mt++) {
                int r0 = (wm + mt * 16 + g) * PITCH + kb + t4;
                int r1 = r0 + 8 * PITCH;
                ahi[mt][0] = AH[r0];
                ahi[mt][1] = AH[r1];
                ahi[mt][2] = AH[r0 + 4];
                ahi[mt][3] = AH[r1 + 4];
            }
            #pragma unroll
            for (int nt = 0; nt < 4; nt++) {
                int rn = (wn + nt * 8 + g) * PITCH + kb + t4;
                bhi[nt][0] = BH[rn];
                bhi[nt][1] = BH[rn + 4];
            }
            // hi*hi
            #pragma unroll
            for (int mt = 0; mt < 4; mt++)
                #pragma unroll
                for (int nt = 0; nt < 4; nt++)
                    mma16(acc[mt][nt], ahi[mt], bhi[nt]);
            // lo*hi
            {
                uint32_t alo[4][4];
                #pragma unroll
                for (int mt = 0; mt < 4; mt++) {
                    int r0 = (wm + mt * 16 + g) * PITCH + kb + t4;
                    int r1 = r0 + 8 * PITCH;
                    alo[mt][0] = AL[r0];
                    alo[mt][1] = AL[r1];
                    alo[mt][2] = AL[r0 + 4];
                    alo[mt][3] = AL[r1 + 4];
                }
                #pragma unroll
                for (int mt = 0; mt < 4; mt++)
                    #pragma unroll
                    for (int nt = 0; nt < 4; nt++)
                        mma16(acc[mt][nt], alo[mt], bhi[nt]);
            }
            // hi*lo
            {
                uint32_t blo[4][2];
                #pragma unroll
                for (int nt = 0; nt < 4; nt++) {
                    int rn = (wn + nt * 8 + g) * PITCH + kb + t4;
                    blo[nt][0] = BL[rn];
                    blo[nt][1] = BL[rn + 4];
                }
                #pragma unroll
                for (int mt = 0; mt < 4; mt++)
                    #pragma unroll
                    for (int nt = 0; nt < 4; nt++)
                        mma16(acc[mt][nt], ahi[mt], blo[nt]);
            }
        }
        __syncthreads();
    }

    // epilogue
    #pragma unroll
    for (int mt = 0; mt < 4; mt++) {
        #pragma unroll
        for (int i = 0; i < 2; i++) {
            int m = bm + wm + mt * 16 + g + i * 8;
            #pragma unroll
            for (int nt = 0; nt < 4; nt++) {
                int n0 = bn + wn + nt * 8 + t4 * 2;
                float vv[2];
                bool ok[2];
                #pragma unroll
                for (int j = 0; j < 2; j++) {
                    int n = n0 + j;
                    ok[j] = (n < N);
                    float v = acc[mt][nt][i * 2 + j];
                    if (ok[j]) {
                        if (bias) v += __ldg(&bias[n]);
                        size_t idx = (size_t)m * N + n;
                        if (EPI == 1) v += C[idx];
                        if (EPI == 2) v += S[idx];
                        C[idx] = v;
                    }
                    vv[j] = v;
                }
                if (SPLIT && ok[1]) {          // SPLIT only used with even N
                    size_t idx = (size_t)m * N + n0;
                    uint32_t h, l;
                    split2(vv[0], vv[1], h, l);
                    *reinterpret_cast<uint32_t*>(Ch + idx) = h;
                    *reinterpret_cast<uint32_t*>(Cl + idx) = l;
                }
            }
        }
    }
}

// ---------------------------------------------------------------------------
// Depthwise conv1d (k=3, pad=1) + SiLU -> h2 hi/lo planes (pairwise)
// ---------------------------------------------------------------------------
__global__ void conv_silu_kernel(const float* __restrict__ h,
                                 const float* __restrict__ cw,
                                 const float* __restrict__ cb,
                                 bf16* __restrict__ oh, bf16* __restrict__ ol) {
    int i = blockIdx.x * blockDim.x + threadIdx.x;     // over MM*DD/2
    if (i >= MM * DD / 2) return;
    const int D2 = DD / 2;
    int row = i / D2;
    int e   = (i - row * D2) * 2;
    int l   = row % LL;
    float2 cur  = reinterpret_cast<const float2*>(h)[i];
    float2 prev = (l > 0)      ? reinterpret_cast<const float2*>(h)[i - D2] : make_float2(0.f, 0.f);
    float2 next = (l < LL - 1) ? reinterpret_cast<const float2*>(h)[i + D2] : make_float2(0.f, 0.f);
    float v0 = prev.x * __ldg(&cw[e * 3 + 0]) + cur.x * __ldg(&cw[e * 3 + 1])
             + next.x * __ldg(&cw[e * 3 + 2]) + __ldg(&cb[e]);
    float v1 = prev.y * __ldg(&cw[e * 3 + 3]) + cur.y * __ldg(&cw[e * 3 + 4])
             + next.y * __ldg(&cw[e * 3 + 5]) + __ldg(&cb[e + 1]);
    v0 = siluf(v0);
    v1 = siluf(v1);
    uint32_t hh, ll2;
    split2(v0, v1, hh, ll2);
    reinterpret_cast<uint32_t*>(oh)[i] = hh;
    reinterpret_cast<uint32_t*>(ol)[i] = ll2;
}

// ---------------------------------------------------------------------------
// A_bar: al <- exp(-softplus(dl) * al)
// ---------------------------------------------------------------------------
__global__ void abar_kernel(const float* __restrict__ dl, float* __restrict__ al) {
    int idx = blockIdx.x * blockDim.x + threadIdx.x;
    if (idx >= MM * DH) return;
    float xdin = dl[idx];
    float xd = fmaxf(xdin, 0.0f) + log1pf(expf(-fabsf(xdin)));
    al[idx] = expf(-xd * al[idx]);
}

// ---------------------------------------------------------------------------
// SSM scan -> hs hi/lo planes
// ---------------------------------------------------------------------------
__global__ void scan_kernel(const float* __restrict__ ab,
                            const float* __restrict__ bl,
                            bf16* __restrict__ hh, bf16* __restrict__ hl) {
    int gid = blockIdx.x * blockDim.x + threadIdx.x;   // 0 .. BB*DH-1
    if (gid >= BB * DH) return;
    int b = gid / DH;
    int h = gid - b * DH;
    size_t base = (size_t)b * LL * DH + h;
    float p = 1.0f, s = 0.0f;
    for (int t = 0; t < LL; t += 4) {
        size_t i = base + (size_t)t * DH;
        float a0 = ab[i], a1 = ab[i + DH], a2 = ab[i + 2 * DH], a3 = ab[i + 3 * DH];
        float b0 = bl[i], b1 = bl[i + DH], b2 = bl[i + 2 * DH], b3 = bl[i + 3 * DH];
        float p0 = p * a0, p1 = p0 * a1, p2 = p1 * a2, p3 = p2 * a3;
        #pragma unroll
        for (int u = 0; u < 4; u++) {
            float pu = (u == 0) ? p0 : (u == 1) ? p1 : (u == 2) ? p2 : p3;
            float bu = (u == 0) ? b0 : (u == 1) ? b1 : (u == 2) ? b2 : b3;
            s = fmaf(bu, pu, s);
            size_t ii = i + (size_t)u * DH;
            bf16 hv = __float2bfloat16_rn(s);
            hh[ii] = hv;
            hl[ii] = __float2bfloat16_rn(s - __bfloat162float(hv));
        }
        p = p3;
    }
}

// ---------------------------------------------------------------------------
// Gate:  gplanes = s * silu(g)   (pairwise)
// ---------------------------------------------------------------------------
__global__ void gate_kernel(const float* __restrict__ s, const float* __restrict__ g,
                            bf16* __restrict__ oh, bf16* __restrict__ ol) {
    int i = blockIdx.x * blockDim.x + threadIdx.x;     // over MM*DD/2
    if (i >= MM * DD / 2) return;
    float2 sv = reinterpret_cast<const float2*>(s)[i];
    float2 gv = reinterpret_cast<const float2*>(g)[i];
    float v0 = sv.x * siluf(gv.x);
    float v1 = sv.y * siluf(gv.y);
    uint32_t hh, ll2;
    split2(v0, v1, hh, ll2);
    reinterpret_cast<uint32_t*>(oh)[i] = hh;
    reinterpret_cast<uint32_t*>(ol)[i] = ll2;
}

// ---------------------------------------------------------------------------
// LayerNorm over last dim (768) -> xn hi/lo planes
// ---------------------------------------------------------------------------
__global__ __launch_bounds__(256)
void ln_kernel(const float* __restrict__ x, const float* __restrict__ gw,
               const float* __restrict__ bw, bf16* __restrict__ yh,
               bf16* __restrict__ yl) {
    int row = blockIdx.x;
    const float* xr = x + (size_t)row * DD;
    int tid = threadIdx.x;

    __shared__ float red[8];
    __shared__ float stat[2];

    float v[3];
    float sum = 0.0f;
    #pragma unroll
    for (int i = 0; i < 3; i++) { v[i] = xr[tid + i * 256]; sum += v[i]; }
    #pragma unroll
    for (int o = 16; o > 0; o >>= 1) sum += __shfl_xor_sync(0xffffffffu, sum, o);
    if ((tid & 31) == 0) red[tid >> 5] = sum;
    __syncthreads();
    if (tid == 0) {
        float t = 0.0f;
        #pragma unroll
        for (int w = 0; w < 8; w++) t += red[w];
        stat[0] = t;
    }
    __syncthreads();
    float mu = stat[0] * (1.0f / (float)DD);

    float vs = 0.0f;
    #pragma unroll
    for (int i = 0; i < 3; i++) { float d = v[i] - mu; vs += d * d; }
    #pragma unroll
    for (int o = 16; o > 0; o >>= 1) vs += __shfl_xor_sync(0xffffffffu, vs, o);
    if ((tid & 31) == 0) red[tid >> 5] = vs;
    __syncthreads();
    if (tid == 0) {
        float t = 0.0f;
        #pragma unroll
        for (int w = 0; w < 8; w++) t += red[w];
        stat[1] = t;
    }
    __syncthreads();
    float rstd = rsqrtf(stat[1] * (1.0f / (float)DD) + 1e-5f);

    #pragma unroll
    for (int i = 0; i < 3; i++) {
        int e = tid + i * 256;
        float r = (v[i] - mu) * rstd * __ldg(&gw[e]) + __ldg(&bw[e]);
        size_t idx = (size_t)row * DD + e;
        bf16 hv = __float2bfloat16_rn(r);
        yh[idx] = hv;
        yl[idx] = __float2bfloat16_rn(r - __bfloat162float(hv));
    }
}

// ---------------------------------------------------------------------------
// Launcher
// ---------------------------------------------------------------------------
extern "C" void kernel_launch(void* const* d_in, const int* in_sizes, int n_in,
                              void* d_out, int out_size) {
    const int*   tokens  = (const int*)  d_in[0];
    const float* embed   = (const float*)d_in[1];
    const float* lin1_w  = (const float*)d_in[2];
    const float* conv_w  = (const float*)d_in[3];
    const float* conv_b  = (const float*)d_in[4];
    const float* A_w     = (const float*)d_in[5];
    const float* A_b     = (const float*)d_in[6];
    const float* B_w     = (const float*)d_in[7];
    const float* B_b     = (const float*)d_in[8];
    const float* del_w   = (const float*)d_in[9];
    const float* del_b   = (const float*)d_in[10];
    const float* C_w     = (const float*)d_in[11];
    const float* C_b     = (const float*)d_in[12];
    const float* D_w     = (const float*)d_in[13];
    const float* D_b     = (const float*)d_in[14];
    const float* lin2_w  = (const float*)d_in[15];
    const float* last_w  = (const float*)d_in[16];
    const float* ln_g    = (const float*)d_in[17];
    const float* ln_b    = (const float*)d_in[18];
    float* out = (float*)d_out;

    float *x, *h1, *s, *g, *dl, *al, *bl;
    cudaGetSymbolAddress((void**)&x,  g_x);
    cudaGetSymbolAddress((void**)&h1, g_h1);
    cudaGetSymbolAddress((void**)&s,  g_s);
    cudaGetSymbolAddress((void**)&g,  g_g);
    cudaGetSymbolAddress((void**)&dl, g_dl);
    cudaGetSymbolAddress((void**)&al, g_al);
    cudaGetSymbolAddress((void**)&bl, g_bl);

    bf16 *xh, *xl, *h2h, *h2l, *sh, *sl, *ggh, *ggl, *xnh, *xnl, *hsh, *hsl;
    cudaGetSymbolAddress((void**)&xh,  x_h);  cudaGetSymbolAddress((void**)&xl,  x_l);
    cudaGetSymbolAddress((void**)&h2h, h2_h); cudaGetSymbolAddress((void**)&h2l, h2_l);
    cudaGetSymbolAddress((void**)&sh,  s_h);  cudaGetSymbolAddress((void**)&sl,  s_l);
    cudaGetSymbolAddress((void**)&ggh, gg_h); cudaGetSymbolAddress((void**)&ggl, gg_l);
    cudaGetSymbolAddress((void**)&xnh, xn_h); cudaGetSymbolAddress((void**)&xnl, xn_l);
    cudaGetSymbolAddress((void**)&hsh, hs_h); cudaGetSymbolAddress((void**)&hsl, hs_l);

    bf16 *p1h, *p1l, *pdh, *pdl, *pah, *pal, *pbh, *pbl, *pch, *pcl;
    bf16 *pDh, *pDl, *p2h, *p2l, *pLh, *pLl, *peh, *pel;
    cudaGetSymbolAddress((void**)&p1h, w1_h); cudaGetSymbolAddress((void**)&p1l, w1_l);
    cudaGetSymbolAddress((void**)&pdh, wd_h); cudaGetSymbolAddress((void**)&pdl, wd_l);
    cudaGetSymbolAddress((void**)&pah, wa_h); cudaGetSymbolAddress((void**)&pal, wa_l);
    cudaGetSymbolAddress((void**)&pbh, wb_h); cudaGetSymbolAddress((void**)&pbl, wb_l);
    cudaGetSymbolAddress((void**)&pch, wc_h); cudaGetSymbolAddress((void**)&pcl, wc_l);
    cudaGetSymbolAddress((void**)&pDh, wD_h); cudaGetSymbolAddress((void**)&pDl, wD_l);
    cudaGetSymbolAddress((void**)&p2h, w2_h); cudaGetSymbolAddress((void**)&p2l, w2_l);
    cudaGetSymbolAddress((void**)&pLh, wL_h); cudaGetSymbolAddress((void**)&pLl, wL_l);
    cudaGetSymbolAddress((void**)&peh, we_h); cudaGetSymbolAddress((void**)&pel, we_l);

    cudaFuncSetAttribute(gemm_bf3<0,false>, cudaFuncAttributeMaxDynamicSharedMemorySize, SMEMB);
    cudaFuncSetAttribute(gemm_bf3<1,true >, cudaFuncAttributeMaxDynamicSharedMemorySize, SMEMB);
    cudaFuncSetAttribute(gemm_bf3<2,true >, cudaFuncAttributeMaxDynamicSharedMemorySize, SMEMB);

    const dim3 blk(256);
    const dim3 gd768((DD + 127) / 128, MM / 128);
    const dim3 gd1536((DH + 127) / 128, MM / 128);
    const dim3 gdV((VV + 127) / 128, MM / 128);

    // ---- weight conversion (once per launch) ----
    const int ndd = NLAY * DD * DD / 4, ndh = NLAY * DH * DD / 4, nem = VV * DD / 4;
    split_kernel<<<(ndd + 255) / 256, 256>>>(lin1_w, p1h, p1l, ndd);
    split_kernel<<<(ndh + 255) / 256, 256>>>(del_w,  pdh, pdl, ndh);
    split_kernel<<<(ndh + 255) / 256, 256>>>(A_w,    pah, pal, ndh);
    split_kernel<<<(ndh + 255) / 256, 256>>>(B_w,    pbh, pbl, ndh);
    split_kernel<<<(ndh + 255) / 256, 256>>>(C_w,    pch, pcl, ndh);
    split_kernel<<<(ndd + 255) / 256, 256>>>(D_w,    pDh, pDl, ndd);
    split_kernel<<<(ndd + 255) / 256, 256>>>(lin2_w, p2h, p2l, ndd);
    split_kernel<<<(ndd + 255) / 256, 256>>>(last_w, pLh, pLl, ndd);
    split_kernel<<<(nem + 255) / 256, 256>>>(embed,  peh, pel, nem);

    embed_kernel<<<(MM * (DD / 4) + 255) / 256, 256>>>(tokens, embed, x, xh, xl);

    for (int i = 0; i < NLAY; i++) {
        size_t odd = (size_t)i * DD * DD, odh = (size_t)i * DH * DD;
        const float* cw  = conv_w + (size_t)i * DD * 3;
        const float* cb  = conv_b + (size_t)i * DD;
        const float* db  = del_b  + (size_t)i * DH;
        const float* ab  = A_b    + (size_t)i * DH;
        const float* bb  = B_b    + (size_t)i * DH;
        const float* cbp = C_b    + (size_t)i * DD;
        const float* dbp = D_b    + (size_t)i * DD;

        // h1 = x @ lin1^T
        gemm_bf3<0,false><<<gd768, blk, SMEMB>>>(xh, xl, p1h + odd, p1l + odd,
            nullptr, nullptr, h1, nullptr, nullptr, MM, DD, DD);
        // h2 planes = silu(conv1d(h1))
        conv_silu_kernel<<<(MM * DD / 2 + 255) / 256, 256>>>(h1, cw, cb, h2h, h2l);
        // delta / A / B projections
        gemm_bf3<0,false><<<gd1536, blk, SMEMB>>>(h2h, h2l, pdh + odh, pdl + odh,
            db, nullptr, dl, nullptr, nullptr, MM, DH, DD);
        gemm_bf3<0,false><<<gd1536, blk, SMEMB>>>(h2h, h2l, pah + odh, pal + odh,
            ab, nullptr, al, nullptr, nullptr, MM, DH, DD);
        gemm_bf3<0,false><<<gd1536, blk, SMEMB>>>(h2h, h2l, pbh + odh, pbl + odh,
            bb, nullptr, bl, nullptr, nullptr, MM, DH, DD);
        // A_bar + scan
        abar_kernel<<<(MM * DH + 255) / 256, 256>>>(dl, al);
        scan_kernel<<<(BB * DH + 255) / 256, 256>>>(al, bl, hsh, hsl);
        // s = hs @ Cw^T + Cb, then s += h2 @ Dw^T + Db (split out s planes)
        gemm_bf3<0,false><<<gd768, blk, SMEMB>>>(hsh, hsl, pch + odh, pcl + odh,
            cbp, nullptr, s, nullptr, nullptr, MM, DD, DH);
        gemm_bf3<1,true ><<<gd768, blk, SMEMB>>>(h2h, h2l, pDh + odd, pDl + odd,
            dbp, nullptr, s, sh, sl, MM, DD, DD);
        // g = s @ lin2^T ; gate
        gemm_bf3<0,false><<<gd768, blk, SMEMB>>>(sh, sl, p2h + odd, p2l + odd,
            nullptr, nullptr, g, nullptr, nullptr, MM, DD, DD);
        gate_kernel<<<(MM * DD / 2 + 255) / 256, 256>>>(s, g, ggh, ggl);
        // x = s + gate @ last^T   (split out x planes for next layer)
        gemm_bf3<2,true ><<<gd768, blk, SMEMB>>>(ggh, ggl, pLh + odd, pLl + odd,
            nullptr, s, x, xh, xl, MM, DD, DD);
    }

    ln_kernel<<<MM, 256>>>(x, ln_g, ln_b, xnh, xnl);
    gemm_bf3<0,false><<<gdV, blk, SMEMB>>>(xnh, xnl, peh, pel,
        nullptr, nullptr, out, nullptr, nullptr, MM, VV, DD);
}

// round 6
// speedup vs baseline: 3.2476x; 1.2393x over previous
#include <cuda_runtime.h>
#include <cuda_bf16.h>
#include <cstdint>
#include <cstddef>

typedef __nv_bfloat16 bf16;

// Problem constants
#define BB   2
#define LL   2048
#define MM   (BB*LL)     // 4096
#define DD   768
#define DH   1536
#define N3   (3*DH)      // 4608 (delta|A|B fused projection)
#define NLAY 8
#define VV   50257
#define NCH  16
#define CHL  (LL/NCH)    // 128

// ---------------------------------------------------------------------------
// Scratch (__device__ globals; no cudaMalloc allowed)
// ---------------------------------------------------------------------------
__device__ float g_x  [MM*DD];
__device__ float g_h1 [MM*DD];
__device__ float g_s  [MM*DD];
__device__ float g_g  [MM*DD];
__device__ float g_dab[(size_t)MM*N3];
__device__ float g_b3 [NLAY*N3];
__device__ float g_cp [BB*NCH*DH];
__device__ float g_cs [BB*NCH*DH];

// Activation hi/lo bf16 planes
__device__ __align__(16) bf16 x_h [MM*DD], x_l [MM*DD];
__device__ __align__(16) bf16 h2_h[MM*DD], h2_l[MM*DD];
__device__ __align__(16) bf16 s_h [MM*DD], s_l [MM*DD];
__device__ __align__(16) bf16 gg_h[MM*DD], gg_l[MM*DD];
__device__ __align__(16) bf16 xn_h[MM*DD], xn_l[MM*DD];
__device__ __align__(16) bf16 hs_h[MM*DH], hs_l[MM*DH];

// Weight hi/lo bf16 planes
__device__ __align__(16) bf16 w1_h  [NLAY*DD*DD],         w1_l  [NLAY*DD*DD];
__device__ __align__(16) bf16 wdab_h[(size_t)NLAY*N3*DD], wdab_l[(size_t)NLAY*N3*DD];
__device__ __align__(16) bf16 wc_h  [NLAY*DD*DH],         wc_l  [NLAY*DD*DH];
__device__ __align__(16) bf16 wD_h  [NLAY*DD*DD],         wD_l  [NLAY*DD*DD];
__device__ __align__(16) bf16 w2_h  [NLAY*DD*DD],         w2_l  [NLAY*DD*DD];
__device__ __align__(16) bf16 wL_h  [NLAY*DD*DD],         wL_l  [NLAY*DD*DD];
__device__ __align__(16) bf16 we_h  [(size_t)VV*DD],      we_l  [(size_t)VV*DD];

__device__ __forceinline__ float siluf(float v) {
    return v * (1.0f / (1.0f + expf(-v)));
}

// Split two floats into packed bf16x2 (low half = x0) hi and lo.
__device__ __forceinline__ void split2(float x0, float x1, uint32_t& hi, uint32_t& lo) {
    asm("cvt.rn.bf16x2.f32 %0, %1, %2;" : "=r"(hi) : "f"(x1), "f"(x0));
    float h0 = __uint_as_float(hi << 16);
    float h1 = __uint_as_float(hi & 0xffff0000u);
    asm("cvt.rn.bf16x2.f32 %0, %1, %2;" : "=r"(lo) : "f"(x1 - h1), "f"(x0 - h0));
}

// ---------------------------------------------------------------------------
// fp32 -> hi/lo bf16 planes
// ---------------------------------------------------------------------------
__global__ void split_kernel(const float* __restrict__ in,
                             bf16* __restrict__ hi, bf16* __restrict__ lo, int n4) {
    int i = blockIdx.x * blockDim.x + threadIdx.x;
    if (i >= n4) return;
    float4 v = reinterpret_cast<const float4*>(in)[i];
    uint32_t h0, l0, h1, l1;
    split2(v.x, v.y, h0, l0);
    split2(v.z, v.w, h1, l1);
    reinterpret_cast<uint2*>(hi)[i] = make_uint2(h0, h1);
    reinterpret_cast<uint2*>(lo)[i] = make_uint2(l0, l1);
}

// Concatenated bias [NLAY][delta|A|B]
__global__ void bias3_kernel(const float* __restrict__ db, const float* __restrict__ ab,
                             const float* __restrict__ bb, float* __restrict__ o) {
    int idx = blockIdx.x * blockDim.x + threadIdx.x;
    if (idx >= NLAY * N3) return;
    int l = idx / N3;
    int r = idx - l * N3;
    int p = r / DH;
    int c = r - p * DH;
    const float* s = (p == 0) ? db : (p == 1) ? ab : bb;
    o[idx] = s[l * DH + c];
}

// ---------------------------------------------------------------------------
// Embedding gather -> x fp32 + hi/lo planes
// ---------------------------------------------------------------------------
__global__ void embed_kernel(const int* __restrict__ tokens,
                             const float* __restrict__ embed,
                             float* __restrict__ x,
                             bf16* __restrict__ xh, bf16* __restrict__ xl) {
    int idx = blockIdx.x * blockDim.x + threadIdx.x;
    const int C4 = DD / 4;
    if (idx >= MM * C4) return;
    int m = idx / C4;
    int c = idx - m * C4;
    int t = tokens[m];
    float4 v = reinterpret_cast<const float4*>(embed + (size_t)t * DD)[c];
    reinterpret_cast<float4*>(x)[idx] = v;
    uint32_t h0, l0, h1, l1;
    split2(v.x, v.y, h0, l0);
    split2(v.z, v.w, h1, l1);
    reinterpret_cast<uint2*>(xh)[idx] = make_uint2(h0, h1);
    reinterpret_cast<uint2*>(xl)[idx] = make_uint2(l0, l1);
}

// ---------------------------------------------------------------------------
// BF16x3 GEMM with pre-split planes + ldmatrix fragment loads.
//   C[M,N] = A[M,K] * W[N,K]^T  via AhWh + AlWh + AhWl MMA passes.
//   EPI 0: C = acc + bias ; EPI 1: C += acc + bias ; EPI 2: C = acc + S
//   SPLIT: also emit hi/lo bf16 planes of the result (requires N even).
// 128x128 tile, BK=32 bf16, 256 thr (8 warps: 2x4 of 64x32), cp.async 2-stage.
// SMEM rows pitch 80B -> conflict-free ldmatrix.
// ---------------------------------------------------------------------------
#define RPITCH 80
#define PLN_B  (128*RPITCH)    // 10240 B per plane
#define STG_B  (4*PLN_B)       // 40960 B per stage
#define GSMEM  (2*STG_B)       // 81920 B

__device__ __forceinline__ uint32_t cvta_s(const void* p) {
    uint32_t a;
    asm("{ .reg .u64 t; cvta.to.shared.u64 t, %1; cvt.u32.u64 %0, t; }" : "=r"(a) : "l"(p));
    return a;
}
__device__ __forceinline__ void cp16(uint32_t sdst, const void* gsrc) {
    asm volatile("cp.async.cg.shared.global [%0], [%1], 16;" :: "r"(sdst), "l"(gsrc));
}
__device__ __forceinline__ void ldsm4(uint32_t* r, uint32_t a) {
    asm volatile("ldmatrix.sync.aligned.m8n8.x4.shared.b16 {%0,%1,%2,%3}, [%4];"
                 : "=r"(r[0]), "=r"(r[1]), "=r"(r[2]), "=r"(r[3]) : "r"(a));
}
__device__ __forceinline__ void mma16(float* c, const uint32_t* a, const uint32_t* b) {
    asm volatile(
        "mma.sync.aligned.m16n8k16.row.col.f32.bf16.bf16.f32 "
        "{%0,%1,%2,%3}, {%4,%5,%6,%7}, {%8,%9}, {%0,%1,%2,%3};"
        : "+f"(c[0]), "+f"(c[1]), "+f"(c[2]), "+f"(c[3])
        : "r"(a[0]), "r"(a[1]), "r"(a[2]), "r"(a[3]), "r"(b[0]), "r"(b[1]));
}

template<int EPI, bool SPLIT>
__global__ __launch_bounds__(256, 2)
void gemm_bf3(const bf16* __restrict__ Ah, const bf16* __restrict__ Al,
              const bf16* __restrict__ Wh, const bf16* __restrict__ Wl,
              const float* __restrict__ bias, const float* __restrict__ S,
              float* __restrict__ C, bf16* __restrict__ Ch, bf16* __restrict__ Cl,
              int M, int N, int K) {
    extern __shared__ char smem[];
    const uint32_t sb = cvta_s(smem);

    const int tid  = threadIdx.x;
    const int warp = tid >> 5;
    const int lane = tid & 31;
    const int g    = lane >> 2;
    const int t4   = lane & 3;
    const int wm   = (warp & 1) * 64;
    const int wn   = (warp >> 1) * 32;
    const int bm   = blockIdx.y * 128;
    const int bn   = blockIdx.x * 128;

    float acc[4][4][4];
    #pragma unroll
    for (int mt = 0; mt < 4; mt++)
        #pragma unroll
        for (int nt = 0; nt < 4; nt++)
            #pragma unroll
            for (int r = 0; r < 4; r++)
                acc[mt][nt][r] = 0.0f;

    const int T = K / 32;

    const bf16* planes[4] = {Ah, Al, Wh, Wl};

    // per-stage loader: 2048 16B chunks, 8 per thread
    auto load_stage = [&](int stage, int k0) {
        #pragma unroll
        for (int i = 0; i < 8; i++) {
            int idx = tid + i * 256;           // 0..2047
            int p   = idx >> 9;                // plane 0..3
            int rem = idx & 511;
            int r   = rem >> 2;                // row 0..127
            int c   = rem & 3;                 // 16B chunk 0..3
            uint32_t d = sb + stage * STG_B + p * PLN_B + r * RPITCH + c * 16;
            size_t grow;
            if (p < 2) grow = (size_t)(bm + r);
            else { int n = bn + r; grow = (size_t)(n < N ? n : 0); }
            cp16(d, planes[p] + grow * (size_t)K + k0 + c * 8);
        }
        asm volatile("cp.async.commit_group;" ::: "memory");
    };

    // lane-relative ldmatrix offsets
    const int aoff = (lane & 15) * RPITCH + ((lane >> 4) & 1) * 16;
    const int boff = (((lane >> 4) & 1) * 8 + (lane & 7)) * RPITCH + ((lane >> 3) & 1) * 16;

    load_stage(0, 0);

    for (int tI = 0; tI < T; tI++) {
        const int s = tI & 1;
        if (tI + 1 < T) {
            load_stage(s ^ 1, (tI + 1) * 32);
            asm volatile("cp.async.wait_group 1;" ::: "memory");
        } else {
            asm volatile("cp.async.wait_group 0;" ::: "memory");
        }
        __syncthreads();

        const uint32_t stg = sb + s * STG_B;
        #pragma unroll
        for (int kb = 0; kb < 2; kb++) {
            const uint32_t kboff = kb * 32;
            uint32_t bhi[4][2];
            // Wh (plane 2): two x4 loads pack ntile pairs
            #pragma unroll
            for (int q = 0; q < 2; q++) {
                uint32_t tb[4];
                ldsm4(tb, stg + 2 * PLN_B + (wn + q * 16) * RPITCH + kboff + boff);
                bhi[2 * q][0] = tb[0]; bhi[2 * q][1] = tb[1];
                bhi[2 * q + 1][0] = tb[2]; bhi[2 * q + 1][1] = tb[3];
            }
            // pass 1: Al * Wh
            {
                uint32_t alo[4][4];
                #pragma unroll
                for (int mt = 0; mt < 4; mt++)
                    ldsm4(alo[mt], stg + PLN_B + (wm + mt * 16) * RPITCH + kboff + aoff);
                #pragma unroll
                for (int mt = 0; mt < 4; mt++)
                    #pragma unroll
                    for (int nt = 0; nt < 4; nt++)
                        mma16(acc[mt][nt], alo[mt], bhi[nt]);
            }
            // pass 2: Ah * Wl
            uint32_t ahi[4][4];
            #pragma unroll
            for (int mt = 0; mt < 4; mt++)
                ldsm4(ahi[mt], stg + (wm + mt * 16) * RPITCH + kboff + aoff);
            {
                uint32_t blo[4][2];
                #pragma unroll
                for (int q = 0; q < 2; q++) {
                    uint32_t tb[4];
                    ldsm4(tb, stg + 3 * PLN_B + (wn + q * 16) * RPITCH + kboff + boff);
                    blo[2 * q][0] = tb[0]; blo[2 * q][1] = tb[1];
                    blo[2 * q + 1][0] = tb[2]; blo[2 * q + 1][1] = tb[3];
                }
                #pragma unroll
                for (int mt = 0; mt < 4; mt++)
                    #pragma unroll
                    for (int nt = 0; nt < 4; nt++)
                        mma16(acc[mt][nt], ahi[mt], blo[nt]);
            }
            // pass 3: Ah * Wh
            #pragma unroll
            for (int mt = 0; mt < 4; mt++)
                #pragma unroll
                for (int nt = 0; nt < 4; nt++)
                    mma16(acc[mt][nt], ahi[mt], bhi[nt]);
        }
        __syncthreads();
    }

    // epilogue
    #pragma unroll
    for (int mt = 0; mt < 4; mt++) {
        #pragma unroll
        for (int i = 0; i < 2; i++) {
            int m = bm + wm + mt * 16 + g + i * 8;
            #pragma unroll
            for (int nt = 0; nt < 4; nt++) {
                int n0 = bn + wn + nt * 8 + t4 * 2;
                float vv[2];
                bool ok[2];
                #pragma unroll
                for (int j = 0; j < 2; j++) {
                    int n = n0 + j;
                    ok[j] = (n < N);
                    float v = acc[mt][nt][i * 2 + j];
                    if (ok[j]) {
                        if (bias) v += __ldg(&bias[n]);
                        size_t idx = (size_t)m * N + n;
                        if (EPI == 1) v += C[idx];
                        if (EPI == 2) v += S[idx];
                        C[idx] = v;
                    }
                    vv[j] = v;
                }
                if (SPLIT && ok[1]) {
                    size_t idx = (size_t)m * N + n0;
                    uint32_t h, l;
                    split2(vv[0], vv[1], h, l);
                    *reinterpret_cast<uint32_t*>(Ch + idx) = h;
                    *reinterpret_cast<uint32_t*>(Cl + idx) = l;
                }
            }
        }
    }
}

// ---------------------------------------------------------------------------
// Depthwise conv1d (k=3, pad=1) + SiLU -> h2 hi/lo planes
// ---------------------------------------------------------------------------
__global__ void conv_silu_kernel(const float* __restrict__ h,
                                 const float* __restrict__ cw,
                                 const float* __restrict__ cb,
                                 bf16* __restrict__ oh, bf16* __restrict__ ol) {
    int i = blockIdx.x * blockDim.x + threadIdx.x;
    if (i >= MM * DD / 2) return;
    const int D2 = DD / 2;
    int row = i / D2;
    int e   = (i - row * D2) * 2;
    int l   = row % LL;
    float2 cur  = reinterpret_cast<const float2*>(h)[i];
    float2 prev = (l > 0)      ? reinterpret_cast<const float2*>(h)[i - D2] : make_float2(0.f, 0.f);
    float2 next = (l < LL - 1) ? reinterpret_cast<const float2*>(h)[i + D2] : make_float2(0.f, 0.f);
    float v0 = prev.x * __ldg(&cw[e * 3 + 0]) + cur.x * __ldg(&cw[e * 3 + 1])
             + next.x * __ldg(&cw[e * 3 + 2]) + __ldg(&cb[e]);
    float v1 = prev.y * __ldg(&cw[e * 3 + 3]) + cur.y * __ldg(&cw[e * 3 + 4])
             + next.y * __ldg(&cw[e * 3 + 5]) + __ldg(&cb[e + 1]);
    v0 = siluf(v0);
    v1 = siluf(v1);
    uint32_t hh, ll2;
    split2(v0, v1, hh, ll2);
    reinterpret_cast<uint32_t*>(oh)[i] = hh;
    reinterpret_cast<uint32_t*>(ol)[i] = ll2;
}

// ---------------------------------------------------------------------------
// A_bar: dab[:,DH+c] <- exp(-softplus(dab[:,c]) * dab[:,DH+c])
// ---------------------------------------------------------------------------
__global__ void abar_kernel(float* __restrict__ dab) {
    int idx = blockIdx.x * blockDim.x + threadIdx.x;
    if (idx >= MM * DH) return;
    int row = idx / DH;
    int col = idx - row * DH;
    size_t base = (size_t)row * N3;
    float xdin = dab[base + col];
    float xd = fmaxf(xdin, 0.0f) + log1pf(expf(-fabsf(xdin)));
    float a = dab[base + DH + col];
    dab[base + DH + col] = expf(-xd * a);
}

// ---------------------------------------------------------------------------
// Chunked scan. Phase 1: per-chunk local products/sums.
// ---------------------------------------------------------------------------
__global__ void scan1_kernel(const float* __restrict__ dab,
                             float* __restrict__ cp, float* __restrict__ cs) {
    int gid = blockIdx.x * blockDim.x + threadIdx.x;   // BB*NCH*DH
    if (gid >= BB * NCH * DH) return;
    int h  = gid % DH;
    int ch = (gid / DH) % NCH;
    int b  = gid / (DH * NCH);
    float p = 1.0f, s = 0.0f;
    for (int t = 0; t < CHL; t++) {
        size_t base = ((size_t)(b * LL + ch * CHL + t)) * N3;
        float a  = dab[base + DH + h];
        float bx = dab[base + 2 * DH + h];
        p *= a;
        s = fmaf(bx, p, s);
    }
    cp[gid] = p;
    cs[gid] = s;
}

// Phase 2: exclusive prefix over chunks (per b,h).
__global__ void scan2_kernel(float* __restrict__ cp, float* __restrict__ cs) {
    int gid = blockIdx.x * blockDim.x + threadIdx.x;   // BB*DH
    if (gid >= BB * DH) return;
    int b = gid / DH;
    int h = gid - b * DH;
    float P = 1.0f, S = 0.0f;
    for (int ch = 0; ch < NCH; ch++) {
        size_t idx = ((size_t)b * NCH + ch) * DH + h;
        float p = cp[idx], s = cs[idx];
        cp[idx] = P;
        cs[idx] = S;
        S = fmaf(P, s, S);
        P *= p;
    }
}

// Phase 3: seeded replay -> hs hi/lo planes.
__global__ void scan3_kernel(const float* __restrict__ dab,
                             const float* __restrict__ cp, const float* __restrict__ cs,
                             bf16* __restrict__ hh, bf16* __restrict__ hl) {
    int gid = blockIdx.x * blockDim.x + threadIdx.x;   // BB*NCH*DH
    if (gid >= BB * NCH * DH) return;
    int h  = gid % DH;
    int ch = (gid / DH) % NCH;
    int b  = gid / (DH * NCH);
    float p = cp[gid];
    float s = cs[gid];
    for (int t = 0; t < CHL; t++) {
        size_t row  = (size_t)(b * LL + ch * CHL + t);
        size_t base = row * N3;
        float a  = dab[base + DH + h];
        float bx = dab[base + 2 * DH + h];
        p *= a;
        s = fmaf(bx, p, s);
        size_t o = row * DH + h;
        bf16 hv = __float2bfloat16_rn(s);
        hh[o] = hv;
        hl[o] = __float2bfloat16_rn(s - __bfloat162float(hv));
    }
}

// ---------------------------------------------------------------------------
// Gate: gplanes = s * silu(g)
// ---------------------------------------------------------------------------
__global__ void gate_kernel(const float* __restrict__ s, const float* __restrict__ g,
                            bf16* __restrict__ oh, bf16* __restrict__ ol) {
    int i = blockIdx.x * blockDim.x + threadIdx.x;
    if (i >= MM * DD / 2) return;
    float2 sv = reinterpret_cast<const float2*>(s)[i];
    float2 gv = reinterpret_cast<const float2*>(g)[i];
    float v0 = sv.x * siluf(gv.x);
    float v1 = sv.y * siluf(gv.y);
    uint32_t hh, ll2;
    split2(v0, v1, hh, ll2);
    reinterpret_cast<uint32_t*>(oh)[i] = hh;
    reinterpret_cast<uint32_t*>(ol)[i] = ll2;
}

// ---------------------------------------------------------------------------
// LayerNorm over last dim (768) -> xn hi/lo planes
// ---------------------------------------------------------------------------
__global__ __launch_bounds__(256)
void ln_kernel(const float* __restrict__ x, const float* __restrict__ gw,
               const float* __restrict__ bw, bf16* __restrict__ yh,
               bf16* __restrict__ yl) {
    int row = blockIdx.x;
    const float* xr = x + (size_t)row * DD;
    int tid = threadIdx.x;

    __shared__ float red[8];
    __shared__ float stat[2];

    float v[3];
    float sum = 0.0f;
    #pragma unroll
    for (int i = 0; i < 3; i++) { v[i] = xr[tid + i * 256]; sum += v[i]; }
    #pragma unroll
    for (int o = 16; o > 0; o >>= 1) sum += __shfl_xor_sync(0xffffffffu, sum, o);
    if ((tid & 31) == 0) red[tid >> 5] = sum;
    __syncthreads();
    if (tid == 0) {
        float t = 0.0f;
        #pragma unroll
        for (int w = 0; w < 8; w++) t += red[w];
        stat[0] = t;
    }
    __syncthreads();
    float mu = stat[0] * (1.0f / (float)DD);

    float vs = 0.0f;
    #pragma unroll
    for (int i = 0; i < 3; i++) { float d = v[i] - mu; vs += d * d; }
    #pragma unroll
    for (int o = 16; o > 0; o >>= 1) vs += __shfl_xor_sync(0xffffffffu, vs, o);
    if ((tid & 31) == 0) red[tid >> 5] = vs;
    __syncthreads();
    if (tid == 0) {
        float t = 0.0f;
        #pragma unroll
        for (int w = 0; w < 8; w++) t += red[w];
        stat[1] = t;
    }
    __syncthreads();
    float rstd = rsqrtf(stat[1] * (1.0f / (float)DD) + 1e-5f);

    #pragma unroll
    for (int i = 0; i < 3; i++) {
        int e = tid + i * 256;
        float r = (v[i] - mu) * rstd * __ldg(&gw[e]) + __ldg(&bw[e]);
        size_t idx = (size_t)row * DD + e;
        bf16 hv = __float2bfloat16_rn(r);
        yh[idx] = hv;
        yl[idx] = __float2bfloat16_rn(r - __bfloat162float(hv));
    }
}

// ---------------------------------------------------------------------------
// Launcher
// ---------------------------------------------------------------------------
extern "C" void kernel_launch(void* const* d_in, const int* in_sizes, int n_in,
                              void* d_out, int out_size) {
    const int*   tokens  = (const int*)  d_in[0];
    const float* embed   = (const float*)d_in[1];
    const float* lin1_w  = (const float*)d_in[2];
    const float* conv_w  = (const float*)d_in[3];
    const float* conv_b  = (const float*)d_in[4];
    const float* A_w     = (const float*)d_in[5];
    const float* A_b     = (const float*)d_in[6];
    const float* B_w     = (const float*)d_in[7];
    const float* B_b     = (const float*)d_in[8];
    const float* del_w   = (const float*)d_in[9];
    const float* del_b   = (const float*)d_in[10];
    const float* C_w     = (const float*)d_in[11];
    const float* C_b     = (const float*)d_in[12];
    const float* D_w     = (const float*)d_in[13];
    const float* D_b     = (const float*)d_in[14];
    const float* lin2_w  = (const float*)d_in[15];
    const float* last_w  = (const float*)d_in[16];
    const float* ln_g    = (const float*)d_in[17];
    const float* ln_b    = (const float*)d_in[18];
    float* out = (float*)d_out;

    float *x, *h1, *s, *g, *dab, *b3, *cp, *cs;
    cudaGetSymbolAddress((void**)&x,   g_x);
    cudaGetSymbolAddress((void**)&h1,  g_h1);
    cudaGetSymbolAddress((void**)&s,   g_s);
    cudaGetSymbolAddress((void**)&g,   g_g);
    cudaGetSymbolAddress((void**)&dab, g_dab);
    cudaGetSymbolAddress((void**)&b3,  g_b3);
    cudaGetSymbolAddress((void**)&cp,  g_cp);
    cudaGetSymbolAddress((void**)&cs,  g_cs);

    bf16 *xh, *xl, *h2h, *h2l, *sh, *sl, *ggh, *ggl, *xnh, *xnl, *hsh, *hsl;
    cudaGetSymbolAddress((void**)&xh,  x_h);  cudaGetSymbolAddress((void**)&xl,  x_l);
    cudaGetSymbolAddress((void**)&h2h, h2_h); cudaGetSymbolAddress((void**)&h2l, h2_l);
    cudaGetSymbolAddress((void**)&sh,  s_h);  cudaGetSymbolAddress((void**)&sl,  s_l);
    cudaGetSymbolAddress((void**)&ggh, gg_h); cudaGetSymbolAddress((void**)&ggl, gg_l);
    cudaGetSymbolAddress((void**)&xnh, xn_h); cudaGetSymbolAddress((void**)&xnl, xn_l);
    cudaGetSymbolAddress((void**)&hsh, hs_h); cudaGetSymbolAddress((void**)&hsl, hs_l);

    bf16 *p1h, *p1l, *pPh, *pPl, *pch, *pcl, *pDh, *pDl, *p2h, *p2l, *pLh, *pLl, *peh, *pel;
    cudaGetSymbolAddress((void**)&p1h, w1_h);   cudaGetSymbolAddress((void**)&p1l, w1_l);
    cudaGetSymbolAddress((void**)&pPh, wdab_h); cudaGetSymbolAddress((void**)&pPl, wdab_l);
    cudaGetSymbolAddress((void**)&pch, wc_h);   cudaGetSymbolAddress((void**)&pcl, wc_l);
    cudaGetSymbolAddress((void**)&pDh, wD_h);   cudaGetSymbolAddress((void**)&pDl, wD_l);
    cudaGetSymbolAddress((void**)&p2h, w2_h);   cudaGetSymbolAddress((void**)&p2l, w2_l);
    cudaGetSymbolAddress((void**)&pLh, wL_h);   cudaGetSymbolAddress((void**)&pLl, wL_l);
    cudaGetSymbolAddress((void**)&peh, we_h);   cudaGetSymbolAddress((void**)&pel, we_l);

    cudaFuncSetAttribute(gemm_bf3<0,false>, cudaFuncAttributeMaxDynamicSharedMemorySize, GSMEM);
    cudaFuncSetAttribute(gemm_bf3<1,true >, cudaFuncAttributeMaxDynamicSharedMemorySize, GSMEM);
    cudaFuncSetAttribute(gemm_bf3<2,true >, cudaFuncAttributeMaxDynamicSharedMemorySize, GSMEM);

    const dim3 blk(256);
    const dim3 gd768(DD / 128, MM / 128);            // 6 x 32
    const dim3 gdP(N3 / 128, MM / 128);              // 36 x 32
    const dim3 gdV((VV + 127) / 128, MM / 128);      // 393 x 32

    // ---- prologue: weight plane conversion ----
    const int ndd = NLAY * DD * DD / 4, ncw = NLAY * DD * DH / 4, nem = VV * DD / 4;
    const int npr = DH * DD / 4;
    split_kernel<<<(ndd + 255) / 256, 256>>>(lin1_w, p1h, p1l, ndd);
    for (int l = 0; l < NLAY; l++) {
        size_t so = (size_t)l * DH * DD;
        split_kernel<<<(npr + 255) / 256, 256>>>(del_w + so, pPh + ((size_t)l*3    )*DH*DD, pPl + ((size_t)l*3    )*DH*DD, npr);
        split_kernel<<<(npr + 255) / 256, 256>>>(A_w   + so, pPh + ((size_t)l*3 + 1)*DH*DD, pPl + ((size_t)l*3 + 1)*DH*DD, npr);
        split_kernel<<<(npr + 255) / 256, 256>>>(B_w   + so, pPh + ((size_t)l*3 + 2)*DH*DD, pPl + ((size_t)l*3 + 2)*DH*DD, npr);
    }
    split_kernel<<<(ncw + 255) / 256, 256>>>(C_w,    pch, pcl, ncw);
    split_kernel<<<(ndd + 255) / 256, 256>>>(D_w,    pDh, pDl, ndd);
    split_kernel<<<(ndd + 255) / 256, 256>>>(lin2_w, p2h, p2l, ndd);
    split_kernel<<<(ndd + 255) / 256, 256>>>(last_w, pLh, pLl, ndd);
    split_kernel<<<(nem + 255) / 256, 256>>>(embed,  peh, pel, nem);
    bias3_kernel<<<(NLAY * N3 + 255) / 256, 256>>>(del_b, A_b, B_b, b3);

    embed_kernel<<<(MM * (DD / 4) + 255) / 256, 256>>>(tokens, embed, x, xh, xl);

    for (int i = 0; i < NLAY; i++) {
        size_t odd = (size_t)i * DD * DD;
        size_t opr = (size_t)i * 3 * DH * DD;
        size_t ocw = (size_t)i * DD * DH;
        const float* cw  = conv_w + (size_t)i * DD * 3;
        const float* cb  = conv_b + (size_t)i * DD;
        const float* cbp = C_b    + (size_t)i * DD;
        const float* dbp = D_b    + (size_t)i * DD;

        // h1 = x @ lin1^T
        gemm_bf3<0,false><<<gd768, blk, GSMEM>>>(xh, xl, p1h + odd, p1l + odd,
            nullptr, nullptr, h1, nullptr, nullptr, MM, DD, DD);
        // h2 planes = silu(conv1d(h1))
        conv_silu_kernel<<<(MM * DD / 2 + 255) / 256, 256>>>(h1, cw, cb, h2h, h2l);
        // fused delta|A|B projection
        gemm_bf3<0,false><<<gdP, blk, GSMEM>>>(h2h, h2l, pPh + opr, pPl + opr,
            b3 + (size_t)i * N3, nullptr, dab, nullptr, nullptr, MM, N3, DD);
        // A_bar + chunked scan
        abar_kernel<<<(MM * DH + 255) / 256, 256>>>(dab);
        scan1_kernel<<<(BB * NCH * DH + 255) / 256, 256>>>(dab, cp, cs);
        scan2_kernel<<<(BB * DH + 255) / 256, 256>>>(cp, cs);
        scan3_kernel<<<(BB * NCH * DH + 255) / 256, 256>>>(dab, cp, cs, hsh, hsl);
        // s = hs @ Cw^T + Cb ; s += h2 @ Dw^T + Db (emit s planes)
        gemm_bf3<0,false><<<gd768, blk, GSMEM>>>(hsh, hsl, pch + ocw, pcl + ocw,
            cbp, nullptr, s, nullptr, nullptr, MM, DD, DH);
        gemm_bf3<1,true ><<<gd768, blk, GSMEM>>>(h2h, h2l, pDh + odd, pDl + odd,
            dbp, nullptr, s, sh, sl, MM, DD, DD);
        // g = s @ lin2^T ; gate
        gemm_bf3<0,false><<<gd768, blk, GSMEM>>>(sh, sl, p2h + odd, p2l + odd,
            nullptr, nullptr, g, nullptr, nullptr, MM, DD, DD);
        gate_kernel<<<(MM * DD / 2 + 255) / 256, 256>>>(s, g, ggh, ggl);
        // x = s + gate @ last^T (emit x planes)
        gemm_bf3<2,true ><<<gd768, blk, GSMEM>>>(ggh, ggl, pLh + odd, pLl + odd,
            nullptr, s, x, xh, xl, MM, DD, DD);
    }

    ln_kernel<<<MM, 256>>>(x, ln_g, ln_b, xnh, xnl);
    gemm_bf3<0,false><<<gdV, blk, GSMEM>>>(xnh, xnl, peh, pel,
        nullptr, nullptr, out, nullptr, nullptr, MM, VV, DD);
}